// round 11
// baseline (speedup 1.0000x reference)
#include <cuda_runtime.h>

// ChamferLoss fused single-pass, B=4, N=M=8192, 3D.
// Pair kernel at the fp32 wide-fma floor: packed f32x2, deterministic partial
// buffers, REDUX.MIN.s32 col reduction + per-block smem col combine.
// R11: partials shrunk 10MB -> 5MB (JT 32, ITILES 8, block-level col slabs).

#define BB 4
#define NPTS 8192
#define MPTS 8192
#define THREADS 128
#define IPT 8
#define KKN (IPT / 2)
#define ITILES (NPTS / (THREADS * IPT))   // 8
#define JT 32
#define JCH (MPTS / JT)                   // 256
#define G 8
#define SLAB4 (BB * NPTS / 4)             // 8192 float4 per slab

typedef unsigned long long u64;

__device__ float g_p1[JT][BB * NPTS];      // row-min partials per j-slab (4 MB)
__device__ float g_p2[ITILES][BB * MPTS];  // col-min partials per i-tile (1 MB)

#define PACK2(o, lo, hi)   asm("mov.b64 %0,{%1,%2};" : "=l"(o) : "f"(lo), "f"(hi))
#define UNPACK2(lo, hi, i) asm("mov.b64 {%0,%1},%2;" : "=f"(lo), "=f"(hi) : "l"(i))
#define FMA2(d, a, b, c)   asm("fma.rn.f32x2 %0,%1,%2,%3;" : "=l"(d) : "l"(a), "l"(b), "l"(c))
#define ADD2(d, a, b)      asm("add.rn.f32x2 %0,%1,%2;" : "=l"(d) : "l"(a), "l"(b))

__global__ void __launch_bounds__(THREADS) chamfer_fused_kernel(
    const float* __restrict__ xyz1, const float* __restrict__ xyz2, float* __restrict__ out)
{
    __shared__ ulonglong2 tA[JCH];   // (-2x,-2x | -2y,-2y)
    __shared__ ulonglong2 tB[JCH];   // (-2z,-2z |  n2, n2)
    __shared__ int colmn[JCH];

    const int tid = threadIdx.x;
    const int lane = tid & 31;
    const int b = blockIdx.z;
    const int iBase = blockIdx.x * (THREADS * IPT);
    const int jBase = blockIdx.y * JCH;
    const float* __restrict__ P = xyz1 + (size_t)b * NPTS * 3;
    const float* __restrict__ Q = xyz2 + (size_t)b * MPTS * 3;

    if (blockIdx.x == 0 && blockIdx.y == 0 && blockIdx.z == 0 && tid == 0)
        out[0] = 0.f;

    u64 ax2[KKN], ay2[KKN], az2[KKN], n12[KKN];
    float mn[IPT];
#pragma unroll
    for (int kk = 0; kk < KKN; kk++) {
        int i0 = iBase + tid + (2 * kk) * THREADS;
        int i1 = iBase + tid + (2 * kk + 1) * THREADS;
        float x0 = P[i0 * 3], y0 = P[i0 * 3 + 1], z0 = P[i0 * 3 + 2];
        float x1 = P[i1 * 3], y1 = P[i1 * 3 + 1], z1 = P[i1 * 3 + 2];
        PACK2(ax2[kk], x0, x1);
        PACK2(ay2[kk], y0, y1);
        PACK2(az2[kk], z0, z1);
        float n0 = fmaf(x0, x0, fmaf(y0, y0, z0 * z0));
        float n1 = fmaf(x1, x1, fmaf(y1, y1, z1 * z1));
        PACK2(n12[kk], n0, n1);
        mn[2 * kk] = 3.4e38f;
        mn[2 * kk + 1] = 3.4e38f;
    }

    for (int jj = tid; jj < JCH; jj += THREADS) {
        int j = jBase + jj;
        float x = Q[j * 3], y = Q[j * 3 + 1], z = Q[j * 3 + 2];
        float n2 = fmaf(x, x, fmaf(y, y, z * z));
        float nx = -2.f * x, ny = -2.f * y, nz = -2.f * z;
        u64 X2, Y2, Z2, W2;
        PACK2(X2, nx, nx);
        PACK2(Y2, ny, ny);
        PACK2(Z2, nz, nz);
        PACK2(W2, n2, n2);
        tA[jj] = make_ulonglong2(X2, Y2);
        tB[jj] = make_ulonglong2(Z2, W2);
        colmn[jj] = 0x7f800000;
    }
    __syncthreads();

    for (int jj0 = 0; jj0 < JCH; jj0 += G) {
        int cvi[G];
#pragma unroll
        for (int g = 0; g < G; g++) {
            ulonglong2 ba = tA[jj0 + g];
            ulonglong2 bb = tB[jj0 + g];
            float c0 = 3.4e38f, c1 = 3.4e38f;
#pragma unroll
            for (int kk = 0; kk < KKN; kk++) {
                u64 w, t;
                ADD2(w, n12[kk], bb.y);        // n1 + n2
                FMA2(t, bb.x, az2[kk], w);     // += -2z*az
                FMA2(t, ba.y, ay2[kk], t);     // += -2y*ay
                FMA2(t, ba.x, ax2[kk], t);     // += -2x*ax -> dist^2 x2
                float t0, t1;
                UNPACK2(t0, t1, t);
                mn[2 * kk]     = fminf(mn[2 * kk], t0);
                mn[2 * kk + 1] = fminf(mn[2 * kk + 1], t1);
                c0 = fminf(c0, t0);
                c1 = fminf(c1, t1);
            }
            cvi[g] = __float_as_int(fmaxf(fminf(c0, c1), 0.f));  // clamp -> s32 order
        }
#pragma unroll
        for (int g = 0; g < G; g++)
            cvi[g] = __reduce_min_sync(0xffffffffu, cvi[g]);
        int myv = cvi[0];
#pragma unroll
        for (int g = 1; g < G; g++)
            if (lane == g) myv = cvi[g];
        if (lane < G)
            atomicMin(&colmn[jj0 + lane], myv);   // spread-address smem, 4 warps combine
    }
    __syncthreads();

    // Col partials: one slab per i-tile block.
    float* __restrict__ colOut = g_p2[blockIdx.x] + b * MPTS + jBase;
    for (int jj = tid; jj < JCH; jj += THREADS)
        colOut[jj] = __int_as_float(colmn[jj]);

    // Row partials: one slab per j block.
    float* __restrict__ rowOut = g_p1[blockIdx.y] + b * NPTS;
#pragma unroll
    for (int kk = 0; kk < KKN; kk++) {
        int i0 = iBase + tid + (2 * kk) * THREADS;
        int i1 = iBase + tid + (2 * kk + 1) * THREADS;
        rowOut[i0] = mn[2 * kk];
        rowOut[i1] = mn[2 * kk + 1];
    }
}

// Reduce: 512 blocks x 256 threads (8 warps).
// Blocks 0..255: row buffer (warp w scans slabs w*4..w*4+3 of 32).
// Blocks 256..511: col buffer (warp w scans slab w of 8).
// col4 = blkLocal*32 + lane -> coalesced 512B per warp per slab.
__global__ void chamfer_reduce_kernel(float* __restrict__ out) {
    __shared__ float4 sm[8][32];
    const int lane = threadIdx.x & 31;
    const int warp = threadIdx.x >> 5;
    const bool isRow = blockIdx.x < 256;
    const int blkLocal = isRow ? blockIdx.x : blockIdx.x - 256;
    const int col4 = blkLocal * 32 + lane;

    float4 m = make_float4(3.4e38f, 3.4e38f, 3.4e38f, 3.4e38f);
    if (isRow) {
        const float4* base = (const float4*)g_p1[0] + col4;
#pragma unroll
        for (int s = 0; s < JT / 8; s++) {
            float4 v = base[(size_t)(warp * (JT / 8) + s) * SLAB4];
            m.x = fminf(m.x, v.x); m.y = fminf(m.y, v.y);
            m.z = fminf(m.z, v.z); m.w = fminf(m.w, v.w);
        }
    } else {
        const float4* base = (const float4*)g_p2[0] + col4;
        float4 v = base[(size_t)warp * SLAB4];
        m.x = v.x; m.y = v.y; m.z = v.z; m.w = v.w;
    }
    sm[warp][lane] = m;
    __syncthreads();

    if (warp == 0) {
        float4 r = sm[0][lane];
#pragma unroll
        for (int w = 1; w < 8; w++) {
            float4 v = sm[w][lane];
            r.x = fminf(r.x, v.x); r.y = fminf(r.y, v.y);
            r.z = fminf(r.z, v.z); r.w = fminf(r.w, v.w);
        }
        float s = ((r.x + r.y) + (r.z + r.w)) * (1.f / (BB * NPTS));
#pragma unroll
        for (int o = 16; o > 0; o >>= 1)
            s += __shfl_down_sync(0xffffffffu, s, o);
        if (lane == 0) atomicAdd(out, s);
    }
}

extern "C" void kernel_launch(void* const* d_in, const int* in_sizes, int n_in,
                              void* d_out, int out_size) {
    const float* xyz1 = (const float*)d_in[0];
    const float* xyz2 = (const float*)d_in[1];
    float* out = (float*)d_out;

    dim3 grid(ITILES, JT, BB);  // (8, 32, 4) = 1024 blocks
    chamfer_fused_kernel<<<grid, THREADS>>>(xyz1, xyz2, out);

    chamfer_reduce_kernel<<<512, 256>>>(out);
}

// round 12
// speedup vs baseline: 1.0613x; 1.0613x over previous
#include <cuda_runtime.h>

// ChamferLoss fused single-pass, B=4, N=M=8192, 3D.
// Pair kernel: EXACT R10 config (THREADS=128, IPT=16, JT=64) — measured at the
// fp32 wide-fma floor (~55us). Packed f32x2, deterministic partial buffers,
// REDUX.MIN.s32 col reduction.
// Reduce v4: 1024x128 grid (pair-grid balance), 16 float4-cols/block,
// 8 slab-shares/block, MLP 8, one atomicAdd per block.

#define BB 4
#define NPTS 8192
#define MPTS 8192
#define THREADS 128
#define IPT 16
#define KKN (IPT / 2)
#define ITILES (NPTS / (THREADS * IPT))   // 4
#define JT 64
#define JCH (MPTS / JT)                   // 128
#define G 8
#define CSLABS (ITILES * 4)               // 16 col slabs
#define SLAB4 (BB * NPTS / 4)             // 8192 float4 per slab

typedef unsigned long long u64;

__device__ float g_p1[JT][BB * NPTS];      // row-min partials per j-slab (8 MB)
__device__ float g_p2[CSLABS][BB * MPTS];  // col-min partials (2 MB)

#define PACK2(o, lo, hi)   asm("mov.b64 %0,{%1,%2};" : "=l"(o) : "f"(lo), "f"(hi))
#define UNPACK2(lo, hi, i) asm("mov.b64 {%0,%1},%2;" : "=f"(lo), "=f"(hi) : "l"(i))
#define FMA2(d, a, b, c)   asm("fma.rn.f32x2 %0,%1,%2,%3;" : "=l"(d) : "l"(a), "l"(b), "l"(c))
#define ADD2(d, a, b)      asm("add.rn.f32x2 %0,%1,%2;" : "=l"(d) : "l"(a), "l"(b))

__global__ void __launch_bounds__(THREADS) chamfer_fused_kernel(
    const float* __restrict__ xyz1, const float* __restrict__ xyz2, float* __restrict__ out)
{
    __shared__ ulonglong2 tA[JCH];
    __shared__ ulonglong2 tB[JCH];

    const int tid = threadIdx.x;
    const int lane = tid & 31;
    const int warp = tid >> 5;
    const int b = blockIdx.z;
    const int iBase = blockIdx.x * (THREADS * IPT);
    const int jBase = blockIdx.y * JCH;
    const float* __restrict__ P = xyz1 + (size_t)b * NPTS * 3;
    const float* __restrict__ Q = xyz2 + (size_t)b * MPTS * 3;

    if (blockIdx.x == 0 && blockIdx.y == 0 && blockIdx.z == 0 && tid == 0)
        out[0] = 0.f;

    u64 ax2[KKN], ay2[KKN], az2[KKN], n12[KKN];
    float mn[IPT];
#pragma unroll
    for (int kk = 0; kk < KKN; kk++) {
        int i0 = iBase + tid + (2 * kk) * THREADS;
        int i1 = iBase + tid + (2 * kk + 1) * THREADS;
        float x0 = P[i0 * 3], y0 = P[i0 * 3 + 1], z0 = P[i0 * 3 + 2];
        float x1 = P[i1 * 3], y1 = P[i1 * 3 + 1], z1 = P[i1 * 3 + 2];
        PACK2(ax2[kk], x0, x1);
        PACK2(ay2[kk], y0, y1);
        PACK2(az2[kk], z0, z1);
        float n0 = fmaf(x0, x0, fmaf(y0, y0, z0 * z0));
        float n1 = fmaf(x1, x1, fmaf(y1, y1, z1 * z1));
        PACK2(n12[kk], n0, n1);
        mn[2 * kk] = 3.4e38f;
        mn[2 * kk + 1] = 3.4e38f;
    }

    for (int jj = tid; jj < JCH; jj += THREADS) {
        int j = jBase + jj;
        float x = Q[j * 3], y = Q[j * 3 + 1], z = Q[j * 3 + 2];
        float n2 = fmaf(x, x, fmaf(y, y, z * z));
        float nx = -2.f * x, ny = -2.f * y, nz = -2.f * z;
        u64 X2, Y2, Z2, W2;
        PACK2(X2, nx, nx);
        PACK2(Y2, ny, ny);
        PACK2(Z2, nz, nz);
        PACK2(W2, n2, n2);
        tA[jj] = make_ulonglong2(X2, Y2);
        tB[jj] = make_ulonglong2(Z2, W2);
    }
    __syncthreads();

    float* __restrict__ colOut = g_p2[blockIdx.x * 4 + warp] + b * MPTS + jBase;

    for (int jj0 = 0; jj0 < JCH; jj0 += G) {
        int cvi[G];
#pragma unroll
        for (int g = 0; g < G; g++) {
            ulonglong2 ba = tA[jj0 + g];
            ulonglong2 bb = tB[jj0 + g];
            float c0 = 3.4e38f, c1 = 3.4e38f;
#pragma unroll
            for (int kk = 0; kk < KKN; kk++) {
                u64 w, t;
                ADD2(w, n12[kk], bb.y);        // n1 + n2
                FMA2(t, bb.x, az2[kk], w);     // += -2z*az
                FMA2(t, ba.y, ay2[kk], t);     // += -2y*ay
                FMA2(t, ba.x, ax2[kk], t);     // += -2x*ax -> dist^2 x2
                float t0, t1;
                UNPACK2(t0, t1, t);
                mn[2 * kk]     = fminf(mn[2 * kk], t0);
                mn[2 * kk + 1] = fminf(mn[2 * kk + 1], t1);
                c0 = fminf(c0, t0);
                c1 = fminf(c1, t1);
            }
            cvi[g] = __float_as_int(fmaxf(fminf(c0, c1), 0.f));
        }
#pragma unroll
        for (int g = 0; g < G; g++)
            cvi[g] = __reduce_min_sync(0xffffffffu, cvi[g]);
        int myv = cvi[0];
#pragma unroll
        for (int g = 1; g < G; g++)
            if (lane == g) myv = cvi[g];
        if (lane < G)
            colOut[jj0 + lane] = __int_as_float(myv);
    }

    float* __restrict__ rowOut = g_p1[blockIdx.y] + b * NPTS;
#pragma unroll
    for (int kk = 0; kk < KKN; kk++) {
        int i0 = iBase + tid + (2 * kk) * THREADS;
        int i1 = iBase + tid + (2 * kk + 1) * THREADS;
        rowOut[i0] = mn[2 * kk];
        rowOut[i1] = mn[2 * kk + 1];
    }
}

// Reduce v4: 1024 blocks x 128 threads (4 warps).
// Blocks 0..511: rows (64 slabs). Blocks 512..1023: cols (16 slabs).
// Block covers 16 float4 columns. share = warp*2 + (lane>>4) in 0..7.
// rows: share scans 8 slabs; cols: share scans 2 slabs.
// Half-warp loads 16 consecutive float4 (256B) -> coalesced.
__global__ void chamfer_reduce_kernel(float* __restrict__ out) {
    __shared__ float4 sm[4][16];
    const int lane = threadIdx.x & 31;
    const int warp = threadIdx.x >> 5;
    const int c = lane & 15;                  // column within block
    const int share = warp * 2 + (lane >> 4); // 0..7
    const bool isRow = blockIdx.x < 512;
    const int blkLocal = isRow ? blockIdx.x : blockIdx.x - 512;
    const int col4 = blkLocal * 16 + c;

    float4 m = make_float4(3.4e38f, 3.4e38f, 3.4e38f, 3.4e38f);
    if (isRow) {
        const float4* base = (const float4*)g_p1[0] + col4;
#pragma unroll
        for (int s = 0; s < 8; s++) {
            float4 v = base[(size_t)(share * 8 + s) * SLAB4];
            m.x = fminf(m.x, v.x); m.y = fminf(m.y, v.y);
            m.z = fminf(m.z, v.z); m.w = fminf(m.w, v.w);
        }
    } else {
        const float4* base = (const float4*)g_p2[0] + col4;
#pragma unroll
        for (int s = 0; s < 2; s++) {
            float4 v = base[(size_t)(share * 2 + s) * SLAB4];
            m.x = fminf(m.x, v.x); m.y = fminf(m.y, v.y);
            m.z = fminf(m.z, v.z); m.w = fminf(m.w, v.w);
        }
    }
    // combine the two half-warp shares (lane xor 16)
    m.x = fminf(m.x, __shfl_xor_sync(0xffffffffu, m.x, 16));
    m.y = fminf(m.y, __shfl_xor_sync(0xffffffffu, m.y, 16));
    m.z = fminf(m.z, __shfl_xor_sync(0xffffffffu, m.z, 16));
    m.w = fminf(m.w, __shfl_xor_sync(0xffffffffu, m.w, 16));
    if (lane < 16) sm[warp][c] = m;
    __syncthreads();

    if (warp == 0 && lane < 16) {
        float4 r = sm[0][c];
#pragma unroll
        for (int w = 1; w < 4; w++) {
            float4 v = sm[w][c];
            r.x = fminf(r.x, v.x); r.y = fminf(r.y, v.y);
            r.z = fminf(r.z, v.z); r.w = fminf(r.w, v.w);
        }
        float s = ((r.x + r.y) + (r.z + r.w)) * (1.f / (BB * NPTS));
#pragma unroll
        for (int o = 8; o > 0; o >>= 1)
            s += __shfl_down_sync(0xffffu, s, o);
        if (lane == 0) atomicAdd(out, s);
    }
}

extern "C" void kernel_launch(void* const* d_in, const int* in_sizes, int n_in,
                              void* d_out, int out_size) {
    const float* xyz1 = (const float*)d_in[0];
    const float* xyz2 = (const float*)d_in[1];
    float* out = (float*)d_out;

    dim3 grid(ITILES, JT, BB);  // (4, 64, 4) = 1024 blocks
    chamfer_fused_kernel<<<grid, THREADS>>>(xyz1, xyz2, out);

    chamfer_reduce_kernel<<<1024, 128>>>(out);
}